// round 12
// baseline (speedup 1.0000x reference)
#include <cuda_runtime.h>
#include <cuda_bf16.h>
#include <cstdint>
#include <math.h>

// Problem constants
#define B_   32
#define C_   64
#define H_   64
#define W_   64
#define K_   128
#define OH_  62
#define OW_  62
#define KHW  9
#define WSZ  576        // C_*KHW
#define NLOC (OH_*OW_)  // 3844
#define Y_ELEMS ((size_t)B_*K_*OH_*OW_)
#define U_ELEMS ((size_t)K_*WSZ)

#define NSTEP 36        // 9 taps * 4 c-chunks of 16

// Scratch (no cudaMalloc allowed)
__device__ int   g_winners[B_*NLOC];
__device__ int   g_list[B_*NLOC];       // per b: locations partitioned by winner k
__device__ int   g_loff[B_*(K_+1)];     // per b: offsets into g_list (129 entries)
__device__ float g_wnormf[K_*WSZ];      // fp32 normalized weights (for fixup rescore)
__device__ uint4 g_w_hi_v[NSTEP*256];   // [step][k*16+cl] bf16, 2048 per step
__device__ uint4 g_w_lo_v[NSTEP*256];

// ---------------------------------------------------------------------------
// Kernel 1: weight norm + 2-way bf16 split into step layout + fp32 copy.
// ---------------------------------------------------------------------------
__global__ void norm_split_kernel(const float* __restrict__ weight) {
    __shared__ float red[256];
    __shared__ float s_nrm;
    int k = blockIdx.x;
    int tid = threadIdx.x;
    const float* wk = weight + (size_t)k * WSZ;

    float s = 0.f;
    for (int e = tid; e < WSZ; e += 256) { float v = wk[e]; s += v * v; }
    red[tid] = s;
    __syncthreads();
    for (int off = 128; off > 0; off >>= 1) {
        if (tid < off) red[tid] += red[tid + off];
        __syncthreads();
    }
    if (tid == 0) {
        float nrm = sqrtf(red[0]);
        if (nrm == 0.f) nrm = 1.f;
        s_nrm = nrm;
    }
    __syncthreads();
    float nrm = s_nrm;

    __nv_bfloat16* wh = (__nv_bfloat16*)g_w_hi_v;
    __nv_bfloat16* wl = (__nv_bfloat16*)g_w_lo_v;
    for (int e = tid; e < WSZ; e += 256) {
        int c = e / 9;
        int u = e - c * 9;            // tap
        int cc = c >> 4, cl = c & 15;
        int step = u * 4 + cc;
        float v = wk[e] / nrm;        // same arithmetic as R0's g_wnorm
        g_wnormf[(size_t)k * WSZ + e] = v;
        __nv_bfloat16 h = __float2bfloat16(v);
        __nv_bfloat16 l = __float2bfloat16(v - __bfloat162float(h));
        wh[step * 2048 + k * 16 + cl] = h;
        wl[step * 2048 + k * 16 + cl] = l;
    }
}

// ---------------------------------------------------------------------------
// Kernel 2: tensor-core conv + bias (3-term bf16 split). No argmax here.
// ---------------------------------------------------------------------------
#define XS_W 66
#define XS_C 66
#define XS_ELEMS (3*XS_W*XS_C)       // 13068 bf16 per buffer
#define WSM_OFF (2*XS_ELEMS)         // 26136
#define SMEM_ELEMS (WSM_OFF + 2*4096)
#define DYNSMEM (SMEM_ELEMS*2)       // 68,656 bytes

#define MMA_BF16(acc, a0,a1,a2,a3, bb0,bb1) \
  asm volatile("mma.sync.aligned.m16n8k16.row.col.f32.bf16.bf16.f32 " \
    "{%0,%1,%2,%3}, {%4,%5,%6,%7}, {%8,%9}, {%0,%1,%2,%3};" \
    : "+f"(acc[0]), "+f"(acc[1]), "+f"(acc[2]), "+f"(acc[3]) \
    : "r"(a0), "r"(a1), "r"(a2), "r"(a3), "r"(bb0), "r"(bb1))

__global__ __launch_bounds__(256, 2)
void conv_tc_kernel(const float* __restrict__ x,
                    const float* __restrict__ bias,
                    float* __restrict__ y) {
    extern __shared__ __nv_bfloat16 smem[];
    __nv_bfloat16* xs_hi = smem;
    __nv_bfloat16* xs_lo = smem + XS_ELEMS;
    __nv_bfloat16* wsm   = smem + WSM_OFF;

    int oh = blockIdx.x;
    int b  = blockIdx.y;
    int tid = threadIdx.x;
    int wid = tid >> 5, lane = tid & 31;
    int wm = wid & 3, wn = wid >> 2;
    int g = lane >> 2, t = lane & 3;

    const float* xb = x + (size_t)b * C_ * H_ * W_;
    for (int l = tid; l < C_ * 3 * W_; l += 256) {
        int w = l & 63;
        int cr = l >> 6;
        int c = cr / 3, r = cr - 3 * c;
        float v = xb[((size_t)c * H_ + (oh + r)) * W_ + w];
        __nv_bfloat16 h = __float2bfloat16(v);
        __nv_bfloat16 lo = __float2bfloat16(v - __bfloat162float(h));
        int o = (r * XS_W + w) * XS_C + c;
        xs_hi[o] = h;
        xs_lo[o] = lo;
    }
    for (int l = tid; l < 3 * 2 * 64; l += 256) {
        int c = l & 63;
        int rz = l >> 6;
        int r = rz >> 1, w = 64 + (rz & 1);
        int o = (r * XS_W + w) * XS_C + c;
        xs_hi[o] = __float2bfloat16(0.f);
        xs_lo[o] = __float2bfloat16(0.f);
    }
    {
        uint4* dsth = (uint4*)(wsm);
        uint4* dstl = (uint4*)(wsm + 2048);
        dsth[tid] = g_w_hi_v[tid];
        dstl[tid] = g_w_lo_v[tid];
    }
    __syncthreads();

    float acc[2][4][4];
#pragma unroll
    for (int mt = 0; mt < 2; mt++)
#pragma unroll
        for (int nt = 0; nt < 4; nt++)
#pragma unroll
            for (int q = 0; q < 4; q++) acc[mt][nt][q] = 0.f;

    const uint32_t* xh32 = (const uint32_t*)xs_hi;
    const uint32_t* xl32 = (const uint32_t*)xs_lo;
    int abase = (wm * 32 + g) * 8 + t;
    int wbase = wn * 32 + g;

    for (int s = 0; s < NSTEP; s++) {
        int buf = s & 1;
        if (s + 1 < NSTEP) {
            uint4* dsth = (uint4*)(wsm + (buf ^ 1) * 4096);
            uint4* dstl = (uint4*)(wsm + (buf ^ 1) * 4096 + 2048);
            dsth[tid] = g_w_hi_v[(s + 1) * 256 + tid];
            dstl[tid] = g_w_lo_v[(s + 1) * 256 + tid];
        }
        const uint32_t* wh = (const uint32_t*)(wsm + buf * 4096);
        const uint32_t* wl = wh + 1024;

        int tap = s >> 2, cc = s & 3;
        int r = tap / 3, sx = tap - 3 * r;

        uint32_t Ah[2][4], Al[2][4];
#pragma unroll
        for (int mt = 0; mt < 2; mt++) {
            int ab = abase + mt * 128;
            Ah[mt][0] = wh[ab];
            Ah[mt][1] = wh[ab + 64];
            Ah[mt][2] = wh[ab + 4];
            Ah[mt][3] = wh[ab + 68];
            Al[mt][0] = wl[ab];
            Al[mt][1] = wl[ab + 64];
            Al[mt][2] = wl[ab + 4];
            Al[mt][3] = wl[ab + 68];
        }

        int bidx0 = (r * XS_W + wbase + sx) * (XS_C / 2) + cc * 8 + t;
#pragma unroll
        for (int nt = 0; nt < 4; nt++) {
            int bi = bidx0 + nt * 8 * (XS_C / 2);
            uint32_t Bh0 = xh32[bi], Bh1 = xh32[bi + 4];
            uint32_t Bl0 = xl32[bi], Bl1 = xl32[bi + 4];
#pragma unroll
            for (int mt = 0; mt < 2; mt++) {
                MMA_BF16(acc[mt][nt], Ah[mt][0], Ah[mt][1], Ah[mt][2], Ah[mt][3], Bh0, Bh1);
                MMA_BF16(acc[mt][nt], Ah[mt][0], Ah[mt][1], Ah[mt][2], Ah[mt][3], Bl0, Bl1);
                MMA_BF16(acc[mt][nt], Al[mt][0], Al[mt][1], Al[mt][2], Al[mt][3], Bh0, Bh1);
            }
        }
        __syncthreads();
    }

    float bb[2][2];
    bb[0][0] = bias[wm * 32 + g];
    bb[0][1] = bias[wm * 32 + g + 8];
    bb[1][0] = bias[wm * 32 + g + 16];
    bb[1][1] = bias[wm * 32 + g + 24];

    float* yb = y + (size_t)b * K_ * NLOC + oh * OW_;

#pragma unroll
    for (int nt = 0; nt < 4; nt++) {
#pragma unroll
        for (int cs = 0; cs < 2; cs++) {
            int ow = wn * 32 + nt * 8 + 2 * t + cs;
            if (ow < OW_) {
#pragma unroll
                for (int mt = 0; mt < 2; mt++) {
#pragma unroll
                    for (int rs = 0; rs < 2; rs++) {
                        int k = wm * 32 + mt * 16 + rs * 8 + g;
                        yb[(size_t)k * NLOC + ow] = acc[mt][nt][rs * 2 + cs] + bb[mt][rs];
                    }
                }
            }
        }
    }
}

// ---------------------------------------------------------------------------
// Kernel 2b: argmax over y; near-ties rescored with the EXACT arithmetic of
// the R0 scalar conv that passed with zero flips: serial fmaf over
// e = c*9 + i*3 + j ascending, then + bias. Bitwise-reproduces R0 scores.
// ---------------------------------------------------------------------------
__global__ __launch_bounds__(64)
void argmax_fixup_kernel(const float* __restrict__ x,
                         const float* __restrict__ bias,
                         const float* __restrict__ y) {
    __shared__ float s_patch[WSZ];
    __shared__ float s_exact[K_];
    __shared__ int   s_flag[64];

    int oh = blockIdx.x;
    int b  = blockIdx.y;
    int tid = threadIdx.x;
    int ow = tid;

    const float* yb = y + (size_t)b * K_ * NLOC + oh * OW_;

    float v1 = -3.402823466e+38f, v2 = -3.402823466e+38f;
    int k1 = 0;
    if (ow < OW_) {
        for (int k = 0; k < K_; k++) {
            float v = yb[(size_t)k * NLOC + ow];
            if (v > v1) { v2 = v1; v1 = v; k1 = k; }      // strict > : first max
            else if (v > v2) { v2 = v; }
        }
    }
    int fix = (ow < OW_) && ((v1 - v2) < 1e-3f * fmaxf(1.0f, fabsf(v1)));
    s_flag[tid] = fix;
    __syncthreads();

    int win = k1;
    for (int f = 0; f < OW_; f++) {
        if (!s_flag[f]) continue;
        // stage patch x[b,:,oh:oh+3,f:f+3] at e = c*9 + i*3 + j
        for (int e = tid; e < WSZ; e += 64) {
            int c = e / 9;
            int u = e - c * 9;
            int r = u / 3, sx = u - 3 * r;
            s_patch[e] = x[(((size_t)b * C_ + c) * H_ + (oh + r)) * W_ + (f + sx)];
        }
        __syncthreads();
        // R0-order serial fmaf chains (two independent chains for ILP)
        {
            int ka = tid, kb = tid + 64;
            const float* wa = g_wnormf + (size_t)ka * WSZ;
            const float* wb = g_wnormf + (size_t)kb * WSZ;
            float sa = 0.f, sb = 0.f;
            for (int e = 0; e < WSZ; e++) {
                float xe = s_patch[e];
                sa = fmaf(xe, wa[e], sa);
                sb = fmaf(xe, wb[e], sb);
            }
            s_exact[ka] = sa + bias[ka];
            s_exact[kb] = sb + bias[kb];
        }
        __syncthreads();
        if (tid == f) {
            float m = s_exact[0];
            int mi = 0;
            for (int k = 1; k < K_; k++)
                if (s_exact[k] > m) { m = s_exact[k]; mi = k; }  // first max
            win = mi;
        }
        __syncthreads();
    }
    if (ow < OW_) g_winners[b * NLOC + oh * OW_ + ow] = win;
}

// ---------------------------------------------------------------------------
// Kernel 3: per-b stable partition of locations by winner k (deterministic).
// ---------------------------------------------------------------------------
__global__ __launch_bounds__(128)
void winner_list_kernel() {
    __shared__ int swin[NLOC];
    __shared__ int sc[128];
    int b = blockIdx.x;
    int tid = threadIdx.x;      // = k

    for (int i = tid; i < NLOC; i += 128) swin[i] = g_winners[b * NLOC + i];
    __syncthreads();

    int cnt = 0;
    for (int i = 0; i < NLOC; i++) cnt += (swin[i] == tid) ? 1 : 0;

    sc[tid] = cnt;
    __syncthreads();
    for (int off = 1; off < 128; off <<= 1) {
        int v = (tid >= off) ? sc[tid - off] : 0;
        __syncthreads();
        sc[tid] += v;
        __syncthreads();
    }
    int end = sc[tid];
    int beg = end - cnt;
    g_loff[b * 129 + tid] = beg;
    if (tid == 127) g_loff[b * 129 + 128] = end;   // == NLOC

    int pos = beg;
    for (int i = 0; i < NLOC; i++) {
        if (swin[i] == tid) g_list[b * NLOC + pos++] = i;
    }
}

// ---------------------------------------------------------------------------
// Kernel 4: Hebbian update, direct. One block per k, 576 threads = (c,r,s).
// ---------------------------------------------------------------------------
__global__ __launch_bounds__(576)
void hebb_kernel(const float* __restrict__ x, float* __restrict__ upd) {
    int k = blockIdx.x;
    int tid = threadIdx.x;
    int c = tid / KHW;
    int u = tid - c * KHW;
    int r = u / 3, s = u - 3 * r;

    float acc = 0.f;
    for (int b = 0; b < B_; b++) {
        int beg = g_loff[b * 129 + k];
        int end = g_loff[b * 129 + k + 1];
        const float* xb = x + ((size_t)b * C_ + c) * H_ * W_ + r * W_ + s;
        const int* lst = g_list + b * NLOC;
        for (int i = beg; i < end; i++) {
            int loc = __ldg(lst + i);
            int h = loc / OW_;
            int w = loc - h * OW_;
            acc += __ldg(xb + h * W_ + w);
        }
    }
    upd[(size_t)k * WSZ + tid] = acc / 123008.0f;   // float32(B*L)+1e-8 == 123008.0f
}

// ---------------------------------------------------------------------------
extern "C" void kernel_launch(void* const* d_in, const int* in_sizes, int n_in,
                              void* d_out, int out_size) {
    const float* x      = (const float*)d_in[0];
    const float* weight = (const float*)d_in[1];
    const float* bias   = (const float*)d_in[2];
    float* out = (float*)d_out;
    float* y   = out;
    float* upd = out + Y_ELEMS;

    cudaFuncSetAttribute(conv_tc_kernel,
                         cudaFuncAttributeMaxDynamicSharedMemorySize, DYNSMEM);

    norm_split_kernel<<<K_, 256>>>(weight);
    conv_tc_kernel<<<dim3(OH_, B_), 256, DYNSMEM>>>(x, bias, y);
    argmax_fixup_kernel<<<dim3(OH_, B_), 64>>>(x, bias, y);
    winner_list_kernel<<<B_, 128>>>();
    hebb_kernel<<<K_, 576>>>(x, upd);
}

// round 13
// speedup vs baseline: 1.2811x; 1.2811x over previous
#include <cuda_runtime.h>
#include <cuda_bf16.h>
#include <cstdint>
#include <math.h>

// Problem constants
#define B_   32
#define C_   64
#define H_   64
#define W_   64
#define K_   128
#define OH_  62
#define OW_  62
#define KHW  9
#define WSZ  576        // C_*KHW
#define NLOC (OH_*OW_)  // 3844
#define Y_ELEMS ((size_t)B_*K_*OH_*OW_)
#define U_ELEMS ((size_t)K_*WSZ)

#define NSTEP 36        // 9 taps * 4 c-chunks of 16
#define NG    8         // hebb b-groups

// Scratch (no cudaMalloc allowed)
__device__ int   g_winners[B_*NLOC];
__device__ int   g_list[B_*NLOC];
__device__ int   g_loff[B_*(K_+1)];
__device__ float g_wnormf[K_*WSZ];
__device__ uint4 g_w_hi_v[NSTEP*256];
__device__ uint4 g_w_lo_v[NSTEP*256];
__device__ int   g_qcount;
__device__ int   g_queue[B_*NLOC];
__device__ float g_hpart[(size_t)NG*K_*WSZ];

// ---------------------------------------------------------------------------
// Kernel 1: weight norm + 2-way bf16 split + fp32 copy. Resets fixup queue.
// ---------------------------------------------------------------------------
__global__ void norm_split_kernel(const float* __restrict__ weight) {
    __shared__ float red[256];
    __shared__ float s_nrm;
    int k = blockIdx.x;
    int tid = threadIdx.x;
    if (k == 0 && tid == 0) g_qcount = 0;
    const float* wk = weight + (size_t)k * WSZ;

    float s = 0.f;
    for (int e = tid; e < WSZ; e += 256) { float v = wk[e]; s += v * v; }
    red[tid] = s;
    __syncthreads();
    for (int off = 128; off > 0; off >>= 1) {
        if (tid < off) red[tid] += red[tid + off];
        __syncthreads();
    }
    if (tid == 0) {
        float nrm = sqrtf(red[0]);
        if (nrm == 0.f) nrm = 1.f;
        s_nrm = nrm;
    }
    __syncthreads();
    float nrm = s_nrm;

    __nv_bfloat16* wh = (__nv_bfloat16*)g_w_hi_v;
    __nv_bfloat16* wl = (__nv_bfloat16*)g_w_lo_v;
    for (int e = tid; e < WSZ; e += 256) {
        int c = e / 9;
        int u = e - c * 9;
        int cc = c >> 4, cl = c & 15;
        int step = u * 4 + cc;
        float v = wk[e] / nrm;        // same arithmetic as R0's g_wnorm
        g_wnormf[(size_t)k * WSZ + e] = v;
        __nv_bfloat16 h = __float2bfloat16(v);
        __nv_bfloat16 l = __float2bfloat16(v - __bfloat162float(h));
        wh[step * 2048 + k * 16 + cl] = h;
        wl[step * 2048 + k * 16 + cl] = l;
    }
}

// ---------------------------------------------------------------------------
// Kernel 2: tensor-core conv + bias (3-term bf16 split). UNCHANGED from R12.
// ---------------------------------------------------------------------------
#define XS_W 66
#define XS_C 66
#define XS_ELEMS (3*XS_W*XS_C)
#define WSM_OFF (2*XS_ELEMS)
#define SMEM_ELEMS (WSM_OFF + 2*4096)
#define DYNSMEM (SMEM_ELEMS*2)

#define MMA_BF16(acc, a0,a1,a2,a3, bb0,bb1) \
  asm volatile("mma.sync.aligned.m16n8k16.row.col.f32.bf16.bf16.f32 " \
    "{%0,%1,%2,%3}, {%4,%5,%6,%7}, {%8,%9}, {%0,%1,%2,%3};" \
    : "+f"(acc[0]), "+f"(acc[1]), "+f"(acc[2]), "+f"(acc[3]) \
    : "r"(a0), "r"(a1), "r"(a2), "r"(a3), "r"(bb0), "r"(bb1))

__global__ __launch_bounds__(256, 2)
void conv_tc_kernel(const float* __restrict__ x,
                    const float* __restrict__ bias,
                    float* __restrict__ y) {
    extern __shared__ __nv_bfloat16 smem[];
    __nv_bfloat16* xs_hi = smem;
    __nv_bfloat16* xs_lo = smem + XS_ELEMS;
    __nv_bfloat16* wsm   = smem + WSM_OFF;

    int oh = blockIdx.x;
    int b  = blockIdx.y;
    int tid = threadIdx.x;
    int wid = tid >> 5, lane = tid & 31;
    int wm = wid & 3, wn = wid >> 2;
    int g = lane >> 2, t = lane & 3;

    const float* xb = x + (size_t)b * C_ * H_ * W_;
    for (int l = tid; l < C_ * 3 * W_; l += 256) {
        int w = l & 63;
        int cr = l >> 6;
        int c = cr / 3, r = cr - 3 * c;
        float v = xb[((size_t)c * H_ + (oh + r)) * W_ + w];
        __nv_bfloat16 h = __float2bfloat16(v);
        __nv_bfloat16 lo = __float2bfloat16(v - __bfloat162float(h));
        int o = (r * XS_W + w) * XS_C + c;
        xs_hi[o] = h;
        xs_lo[o] = lo;
    }
    for (int l = tid; l < 3 * 2 * 64; l += 256) {
        int c = l & 63;
        int rz = l >> 6;
        int r = rz >> 1, w = 64 + (rz & 1);
        int o = (r * XS_W + w) * XS_C + c;
        xs_hi[o] = __float2bfloat16(0.f);
        xs_lo[o] = __float2bfloat16(0.f);
    }
    {
        uint4* dsth = (uint4*)(wsm);
        uint4* dstl = (uint4*)(wsm + 2048);
        dsth[tid] = g_w_hi_v[tid];
        dstl[tid] = g_w_lo_v[tid];
    }
    __syncthreads();

    float acc[2][4][4];
#pragma unroll
    for (int mt = 0; mt < 2; mt++)
#pragma unroll
        for (int nt = 0; nt < 4; nt++)
#pragma unroll
            for (int q = 0; q < 4; q++) acc[mt][nt][q] = 0.f;

    const uint32_t* xh32 = (const uint32_t*)xs_hi;
    const uint32_t* xl32 = (const uint32_t*)xs_lo;
    int abase = (wm * 32 + g) * 8 + t;
    int wbase = wn * 32 + g;

    for (int s = 0; s < NSTEP; s++) {
        int buf = s & 1;
        if (s + 1 < NSTEP) {
            uint4* dsth = (uint4*)(wsm + (buf ^ 1) * 4096);
            uint4* dstl = (uint4*)(wsm + (buf ^ 1) * 4096 + 2048);
            dsth[tid] = g_w_hi_v[(s + 1) * 256 + tid];
            dstl[tid] = g_w_lo_v[(s + 1) * 256 + tid];
        }
        const uint32_t* wh = (const uint32_t*)(wsm + buf * 4096);
        const uint32_t* wl = wh + 1024;

        int tap = s >> 2, cc = s & 3;
        int r = tap / 3, sx = tap - 3 * r;

        uint32_t Ah[2][4], Al[2][4];
#pragma unroll
        for (int mt = 0; mt < 2; mt++) {
            int ab = abase + mt * 128;
            Ah[mt][0] = wh[ab];
            Ah[mt][1] = wh[ab + 64];
            Ah[mt][2] = wh[ab + 4];
            Ah[mt][3] = wh[ab + 68];
            Al[mt][0] = wl[ab];
            Al[mt][1] = wl[ab + 64];
            Al[mt][2] = wl[ab + 4];
            Al[mt][3] = wl[ab + 68];
        }

        int bidx0 = (r * XS_W + wbase + sx) * (XS_C / 2) + cc * 8 + t;
#pragma unroll
        for (int nt = 0; nt < 4; nt++) {
            int bi = bidx0 + nt * 8 * (XS_C / 2);
            uint32_t Bh0 = xh32[bi], Bh1 = xh32[bi + 4];
            uint32_t Bl0 = xl32[bi], Bl1 = xl32[bi + 4];
#pragma unroll
            for (int mt = 0; mt < 2; mt++) {
                MMA_BF16(acc[mt][nt], Ah[mt][0], Ah[mt][1], Ah[mt][2], Ah[mt][3], Bh0, Bh1);
                MMA_BF16(acc[mt][nt], Ah[mt][0], Ah[mt][1], Ah[mt][2], Ah[mt][3], Bl0, Bl1);
                MMA_BF16(acc[mt][nt], Al[mt][0], Al[mt][1], Al[mt][2], Al[mt][3], Bh0, Bh1);
            }
        }
        __syncthreads();
    }

    float bb[2][2];
    bb[0][0] = bias[wm * 32 + g];
    bb[0][1] = bias[wm * 32 + g + 8];
    bb[1][0] = bias[wm * 32 + g + 16];
    bb[1][1] = bias[wm * 32 + g + 24];

    float* yb = y + (size_t)b * K_ * NLOC + oh * OW_;

#pragma unroll
    for (int nt = 0; nt < 4; nt++) {
#pragma unroll
        for (int cs = 0; cs < 2; cs++) {
            int ow = wn * 32 + nt * 8 + 2 * t + cs;
            if (ow < OW_) {
#pragma unroll
                for (int mt = 0; mt < 2; mt++) {
#pragma unroll
                    for (int rs = 0; rs < 2; rs++) {
                        int k = wm * 32 + mt * 16 + rs * 8 + g;
                        yb[(size_t)k * NLOC + ow] = acc[mt][nt][rs * 2 + cs] + bb[mt][rs];
                    }
                }
            }
        }
    }
}

// ---------------------------------------------------------------------------
// Kernel 2b: argmax over y; flagged near-ties appended to global queue.
// ---------------------------------------------------------------------------
__global__ __launch_bounds__(64)
void argmax_flag_kernel(const float* __restrict__ y) {
    int oh = blockIdx.x;
    int b  = blockIdx.y;
    int ow = threadIdx.x;
    if (ow >= OW_) return;

    const float* yb = y + (size_t)b * K_ * NLOC + oh * OW_;

    float v1 = -3.402823466e+38f, v2 = -3.402823466e+38f;
    int k1 = 0;
    for (int k = 0; k < K_; k++) {
        float v = yb[(size_t)k * NLOC + ow];
        if (v > v1) { v2 = v1; v1 = v; k1 = k; }      // strict > : first max
        else if (v > v2) { v2 = v; }
    }
    int loc = oh * OW_ + ow;
    g_winners[b * NLOC + loc] = k1;
    if ((v1 - v2) < 1e-3f * fmaxf(1.0f, fabsf(v1))) {
        int pos = atomicAdd(&g_qcount, 1);           // order-independent final state
        g_queue[pos] = b * NLOC + loc;
    }
}

// ---------------------------------------------------------------------------
// Kernel 2c: rescore flagged entries with R0's exact serial-fmaf arithmetic
// (e = c*9 + i*3 + j ascending, then + bias; first-max over ascending k).
// Block = queue entry, thread = channel k. Writes are per-entry independent.
// ---------------------------------------------------------------------------
__global__ __launch_bounds__(128)
void rescore_kernel(const float* __restrict__ x,
                    const float* __restrict__ bias) {
    __shared__ float s_patch[WSZ];
    __shared__ float s_sc[K_];

    int tid = threadIdx.x;
    int n = g_qcount;
    for (int e = blockIdx.x; e < n; e += gridDim.x) {
        int ent = g_queue[e];
        int b = ent / NLOC;
        int loc = ent - b * NLOC;
        int oh = loc / OW_, ow = loc - oh * OW_;

        for (int i = tid; i < WSZ; i += 128) {
            int c = i / 9;
            int u = i - c * 9;
            int r = u / 3, sx = u - 3 * r;
            s_patch[i] = x[(((size_t)b * C_ + c) * H_ + (oh + r)) * W_ + (ow + sx)];
        }
        __syncthreads();
        {
            const float* wr = g_wnormf + (size_t)tid * WSZ;
            float sa = 0.f;
            for (int i = 0; i < WSZ; i++)
                sa = fmaf(s_patch[i], wr[i], sa);    // serial chain, R0 order
            s_sc[tid] = sa + bias[tid];
        }
        __syncthreads();
        if (tid == 0) {
            float m = s_sc[0];
            int mi = 0;
            for (int k = 1; k < K_; k++)
                if (s_sc[k] > m) { m = s_sc[k]; mi = k; }   // first max
            g_winners[ent] = mi;
        }
        __syncthreads();
    }
}

// ---------------------------------------------------------------------------
// Kernel 3: per-b stable partition by winner, histogram-parallel.
// One block per b, 128 slice-threads. Deterministic (ascending loc within k).
// Dynamic smem: swin[NLOC] + hist[128][128] + counts[128] + kbeg[129]
// ---------------------------------------------------------------------------
#define SL 31                         // ceil(3844/128) = 31
#define WL_SWIN   0
#define WL_HIST   (NLOC + 12)         // pad to 16B align (3856 ints)
#define WL_CNT    (WL_HIST + 128*128)
#define WL_KBEG   (WL_CNT + 128)
#define WL_INTS   (WL_KBEG + 132)
#define WL_SMEM   (WL_INTS*4)         // ~82 KB

__global__ __launch_bounds__(128)
void winner_list_kernel() {
    extern __shared__ int wsmem[];
    int* swin = wsmem + WL_SWIN;
    int* hist = wsmem + WL_HIST;      // [slice][k]
    int* cnts = wsmem + WL_CNT;
    int* kbeg = wsmem + WL_KBEG;

    int b = blockIdx.x;
    int s = threadIdx.x;

    for (int i = s; i < NLOC; i += 128) swin[i] = g_winners[b * NLOC + i];
    for (int k = 0; k < 128; k++) hist[s * 128 + k] = 0;
    __syncthreads();

    int lo = s * SL;
    int hi = min(lo + SL, NLOC);
    for (int i = lo; i < hi; i++) hist[s * 128 + swin[i]]++;
    __syncthreads();

    // column scan: per k, exclusive prefix over slices; total count
    {
        int k = s;
        int run = 0;
        for (int sl = 0; sl < 128; sl++) {
            int t = hist[sl * 128 + k];
            hist[sl * 128 + k] = run;
            run += t;
        }
        cnts[k] = run;
    }
    __syncthreads();

    // exclusive prefix over k (Hillis-Steele on 128)
    {
        int v = cnts[s];
        int acc = v;
        for (int off = 1; off < 128; off <<= 1) {
            int add = (s >= off) ? 0 : 0;
            (void)add;
            int other = (s >= off) ? cnts[s - off] : 0;
            __syncthreads();
            acc += other;
            cnts[s] = acc;
            __syncthreads();
        }
        kbeg[s] = acc - v;            // exclusive
        if (s == 127) kbeg[128] = acc;
        g_loff[b * 129 + s] = acc - v;
        if (s == 127) g_loff[b * 129 + 128] = acc;
    }
    __syncthreads();

    // emit: stable within slice (ascending loc), offsets = kbeg + slice prefix
    for (int i = lo; i < hi; i++) {
        int k = swin[i];
        int pos = kbeg[k] + hist[s * 128 + k];
        hist[s * 128 + k]++;
        g_list[b * NLOC + pos] = i;
    }
}

// ---------------------------------------------------------------------------
// Kernel 4a: Hebbian partials over b-groups. Grid (K_, NG), 576 threads.
// ---------------------------------------------------------------------------
__global__ __launch_bounds__(576)
void hebb_group_kernel(const float* __restrict__ x) {
    int k = blockIdx.x;
    int gidx = blockIdx.y;
    int tid = threadIdx.x;
    int c = tid / KHW;
    int u = tid - c * KHW;
    int r = u / 3, s = u - 3 * r;

    float acc = 0.f;
    int b0 = gidx * (B_ / NG);
    for (int b = b0; b < b0 + B_ / NG; b++) {
        int beg = g_loff[b * 129 + k];
        int end = g_loff[b * 129 + k + 1];
        const float* xb = x + ((size_t)b * C_ + c) * H_ * W_ + r * W_ + s;
        const int* lst = g_list + b * NLOC;
        for (int i = beg; i < end; i++) {
            int loc = __ldg(lst + i);
            int h = loc / OW_;
            int w = loc - h * OW_;
            acc += __ldg(xb + h * W_ + w);
        }
    }
    g_hpart[((size_t)gidx * K_ + k) * WSZ + tid] = acc;
}

// ---------------------------------------------------------------------------
// Kernel 4b: reduce groups, scale.
// ---------------------------------------------------------------------------
__global__ void hebb_reduce_kernel(float* __restrict__ upd) {
    int idx = blockIdx.x * blockDim.x + threadIdx.x;
    if (idx >= (int)U_ELEMS) return;
    float s = 0.f;
    for (int g = 0; g < NG; g++)
        s += g_hpart[(size_t)g * U_ELEMS + idx];
    upd[idx] = s / 123008.0f;   // float32(B*L)+1e-8 == 123008.0f in fp32
}

// ---------------------------------------------------------------------------
extern "C" void kernel_launch(void* const* d_in, const int* in_sizes, int n_in,
                              void* d_out, int out_size) {
    const float* x      = (const float*)d_in[0];
    const float* weight = (const float*)d_in[1];
    const float* bias   = (const float*)d_in[2];
    float* out = (float*)d_out;
    float* y   = out;
    float* upd = out + Y_ELEMS;

    cudaFuncSetAttribute(conv_tc_kernel,
                         cudaFuncAttributeMaxDynamicSharedMemorySize, DYNSMEM);
    cudaFuncSetAttribute(winner_list_kernel,
                         cudaFuncAttributeMaxDynamicSharedMemorySize, WL_SMEM);

    norm_split_kernel<<<K_, 256>>>(weight);
    conv_tc_kernel<<<dim3(OH_, B_), 256, DYNSMEM>>>(x, bias, y);
    argmax_flag_kernel<<<dim3(OH_, B_), 64>>>(y);
    rescore_kernel<<<2048, 128>>>(x, bias);
    winner_list_kernel<<<B_, 128, WL_SMEM>>>();
    hebb_group_kernel<<<dim3(K_, NG), 576>>>(x);
    hebb_reduce_kernel<<<(int)((U_ELEMS + 255) / 256), 256>>>(upd);
}